// round 1
// baseline (speedup 1.0000x reference)
#include <cuda_runtime.h>
#include <cstdint>

// FrozenBNBEmbedding: out[t, d] = code[ weight[input[t], d] ] * absmax[input[t]]
// DIM == BLOCK == 4096, so the per-block absmax index equals the vocab row index.
//
// Inputs (metadata order):
//   d_in[0] = input  : int32 [4, 2048]          (8192 token ids)
//   d_in[1] = weight : int32 [50400, 4096]      (int8 codes stored as int32)
//   d_in[2] = absmax : float32 [50400]          (per-row scale; n_blocks == VOCAB)
//   d_in[3] = code   : float32 [256]            (LUT)
//   d_out   = float32 [4, 2048, 4096]

#define DIM 4096
#define NTOKENS 8192
#define THREADS 256

__global__ __launch_bounds__(THREADS)
void bnb_embed_kernel(const int* __restrict__ input,
                      const int* __restrict__ weight,
                      const float* __restrict__ absmax,
                      const float* __restrict__ code,
                      float* __restrict__ out)
{
    __shared__ float s_code[256];
    s_code[threadIdx.x] = code[threadIdx.x];  // THREADS == 256
    __syncthreads();

    const int t = blockIdx.x;                 // token index 0..8191
    const int tok = input[t];                 // vocab row
    const float scale = __ldg(&absmax[tok]);

    const int4* __restrict__ wrow =
        reinterpret_cast<const int4*>(weight + (size_t)tok * DIM);
    float4* __restrict__ orow =
        reinterpret_cast<float4*>(out + (size_t)t * DIM);

    // 4096 elems / 4 per int4 = 1024 vectors; 256 threads -> 4 iters.
    #pragma unroll
    for (int i = threadIdx.x; i < DIM / 4; i += THREADS) {
        int4 q = wrow[i];
        float4 o;
        o.x = s_code[q.x & 0xFF] * scale;
        o.y = s_code[q.y & 0xFF] * scale;
        o.z = s_code[q.z & 0xFF] * scale;
        o.w = s_code[q.w & 0xFF] * scale;
        orow[i] = o;
    }
}

extern "C" void kernel_launch(void* const* d_in, const int* in_sizes, int n_in,
                              void* d_out, int out_size)
{
    const int*   input  = (const int*)  d_in[0];
    const int*   weight = (const int*)  d_in[1];
    const float* absmax = (const float*)d_in[2];
    const float* code   = (const float*)d_in[3];
    float*       out    = (float*)d_out;

    bnb_embed_kernel<<<NTOKENS, THREADS>>>(input, weight, absmax, code, out);
}